// round 5
// baseline (speedup 1.0000x reference)
#include <cuda_runtime.h>
#include <cuda_bf16.h>
#include <math.h>

// Shapes fixed by the problem
#define NN     1024
#define LL     30
#define GG     10000
#define NBATCH 64
#define GT     256     // genes per block
#define CH     32      // cells per chunk staged in shared

// Scratch (allocation-free rule: __device__ globals)
__device__ int g_order[NN];
__device__ int g_bstart[NBATCH + 1];

// ---------------------------------------------------------------------------
// Kernel 1: counting-sort cells by batch (1 block, N threads). Output order
// within a batch is nondeterministic (atomics) but each cell writes its own
// output row, so the final result is deterministic.
// ---------------------------------------------------------------------------
__global__ void sort_cells_kernel(const int* __restrict__ bc) {
    __shared__ int cnt[NBATCH];
    __shared__ int start[NBATCH + 1];
    __shared__ int cur[NBATCH];
    int t = threadIdx.x;
    if (t < NBATCH) cnt[t] = 0;
    __syncthreads();
    int b = bc[t];
    atomicAdd(&cnt[b], 1);
    __syncthreads();
    if (t == 0) {
        int s = 0;
        for (int i = 0; i < NBATCH; i++) { start[i] = s; s += cnt[i]; }
        start[NBATCH] = s;
    }
    __syncthreads();
    if (t < NBATCH) cur[t] = start[t];
    __syncthreads();
    int p = atomicAdd(&cur[b], 1);
    g_order[p] = t;
    if (t <= NBATCH) g_bstart[t] = start[t];
}

// ---------------------------------------------------------------------------
// Kernel 2: main decoder. Grid = (ceil(G/GT), NB). Each block owns one batch b
// and one gene tile. It stages A_emb[b, g0:g0+GT, :] in shared (contiguous,
// coalesced), folds W into per-thread registers C[l] = W[l,g] + A[b,g,l],
// then streams the cells of batch b in chunks of CH, doing a 30-FMA dot per
// (cell, gene) with z broadcast from shared.
// ---------------------------------------------------------------------------
__global__ __launch_bounds__(GT)
void decoder_kernel(const float* __restrict__ z,
                    const float* __restrict__ sf,
                    const float* __restrict__ W,
                    const float* __restrict__ A,
                    const float* __restrict__ bemb,
                    float* __restrict__ out) {
    __shared__ float Ash[GT * LL];   // 30720 B
    __shared__ float zsh[CH * LL];   // 3840 B
    __shared__ float sfsh[CH];
    __shared__ int   nsh[CH];

    const int tid = threadIdx.x;
    const int g0  = blockIdx.x * GT;
    const int b   = blockIdx.y;
    const int gt  = min(GT, GG - g0);

    // Stage A tile: contiguous gt*30 floats, fully coalesced
    const float* Abase = A + ((size_t)b * GG + g0) * LL;
    for (int i = tid; i < gt * LL; i += GT) Ash[i] = Abase[i];
    __syncthreads();

    const int g  = g0 + tid;
    const bool act = (tid < gt);

    float C[LL];
    float bb = 0.f;
    if (act) {
#pragma unroll
        for (int l = 0; l < LL; l++)
            C[l] = Ash[tid * LL + l] + W[l * GG + g];   // fold h1 into h2
        bb = bemb[(size_t)b * GG + g];
    }

    const int s = g_bstart[b];
    const int e = g_bstart[b + 1];

    for (int c0 = s; c0 < e; c0 += CH) {
        const int nch = min(CH, e - c0);
        __syncthreads();   // zsh reuse safety
        // stage z rows of this cell chunk
        for (int i = tid; i < nch * LL; i += GT) {
            int j = i / LL, l = i - j * LL;
            int n = g_order[c0 + j];
            zsh[i] = z[n * LL + l];
        }
        if (tid < nch) {
            int n = g_order[c0 + tid];
            nsh[tid]  = n;
            sfsh[tid] = sf[n];
        }
        __syncthreads();

        if (act) {
            for (int j = 0; j < nch; j++) {
                const float2* zp = (const float2*)&zsh[j * LL];  // 30 even, aligned
                float acc = bb;
#pragma unroll
                for (int l = 0; l < LL / 2; l++) {
                    float2 zv = zp[l];                 // broadcast LDS.64
                    acc = fmaf(C[2 * l],     zv.x, acc);
                    acc = fmaf(C[2 * l + 1], zv.y, acc);
                }
                // softplus (numerically stable; x is O(1) here)
                float sp = fmaxf(acc, 0.f) + log1pf(__expf(-fabsf(acc)));
                out[(size_t)nsh[j] * GG + g] = sp * sfsh[j];
            }
        }
    }
}

// ---------------------------------------------------------------------------
// Kernel 3: inverse dispersion tail: out[N*G + i] = exp(px_r[i])
// ---------------------------------------------------------------------------
__global__ void invdisp_kernel(const float* __restrict__ px_r,
                               float* __restrict__ out) {
    int i = blockIdx.x * blockDim.x + threadIdx.x;
    if (i < GG) out[(size_t)NN * GG + i] = expf(px_r[i]);
}

// ---------------------------------------------------------------------------
// Launch. Inputs per metadata order:
//   0: z [N,L] f32        1: batch_covariate [N] i32   2: size_factor [N,1] f32
//   3: W_amat [L,G] f32   4: A_emb [NB,G,L] f32        5: b_emb [NB,G] f32
//   6: px_r [G] f32
// Output: mean [N,G] f32 followed by inverse_dispersion [G] f32.
// ---------------------------------------------------------------------------
extern "C" void kernel_launch(void* const* d_in, const int* in_sizes, int n_in,
                              void* d_out, int out_size) {
    const float* z    = (const float*)d_in[0];
    const int*   bc   = (const int*)  d_in[1];
    const float* sf   = (const float*)d_in[2];
    const float* W    = (const float*)d_in[3];
    const float* A    = (const float*)d_in[4];
    const float* bemb = (const float*)d_in[5];
    const float* pxr  = (const float*)d_in[6];
    float* out = (float*)d_out;

    sort_cells_kernel<<<1, NN>>>(bc);

    dim3 grid((GG + GT - 1) / GT, NBATCH);
    decoder_kernel<<<grid, GT>>>(z, sf, W, A, bemb, out);

    invdisp_kernel<<<(GG + 255) / 256, 256>>>(pxr, out);
}

// round 6
// speedup vs baseline: 1.0900x; 1.0900x over previous
#include <cuda_runtime.h>
#include <cuda_bf16.h>
#include <math.h>

// Shapes fixed by the problem
#define NN     1024
#define LL     30
#define LP     32      // padded latent (2 zero lanes)
#define GG     10000
#define NBATCH 64
#define GT     256     // genes per block
#define CH     32      // cells per chunk staged in shared

// Scratch (allocation-free rule: __device__ globals)
__device__ int g_order[NN];
__device__ int g_bstart[NBATCH + 1];

// ---- packed f32x2 helpers (sm_103a) ---------------------------------------
#define FMA2(d, a, b, c) \
    asm("fma.rn.f32x2 %0, %1, %2, %3;" : "=l"(d) : "l"(a), "l"(b), "l"(c))
#define PACK2(d, lo, hi) \
    asm("mov.b64 %0, {%1, %2};" : "=l"(d) : "f"(lo), "f"(hi))
#define UNPACK2(lo, hi, s) \
    asm("mov.b64 {%0, %1}, %2;" : "=f"(lo), "=f"(hi) : "l"(s))

// ---------------------------------------------------------------------------
// Kernel 1: fused prep. Blocks 0..39: inverse dispersion tail exp(px_r).
// Block 40: counting-sort of cells by batch (256 threads x 4 cells).
// ---------------------------------------------------------------------------
__global__ void prep_kernel(const int* __restrict__ bc,
                            const float* __restrict__ px_r,
                            float* __restrict__ out) {
    if (blockIdx.x < 40) {
        int i = blockIdx.x * 256 + threadIdx.x;
        if (i < GG) out[(size_t)NN * GG + i] = __expf(px_r[i]);
        return;
    }
    // sort block
    __shared__ int cnt[NBATCH];
    __shared__ int start[NBATCH + 1];
    __shared__ int cur[NBATCH];
    int t = threadIdx.x;
    if (t < NBATCH) cnt[t] = 0;
    __syncthreads();
    int myb[4];
#pragma unroll
    for (int q = 0; q < 4; q++) {
        myb[q] = bc[t + q * 256];
        atomicAdd(&cnt[myb[q]], 1);
    }
    __syncthreads();
    if (t == 0) {
        int s = 0;
        for (int i = 0; i < NBATCH; i++) { start[i] = s; s += cnt[i]; }
        start[NBATCH] = s;
    }
    __syncthreads();
    if (t < NBATCH) cur[t] = start[t];
    __syncthreads();
#pragma unroll
    for (int q = 0; q < 4; q++) {
        int p = atomicAdd(&cur[myb[q]], 1);
        g_order[p] = t + q * 256;
    }
    if (t <= NBATCH) g_bstart[t] = start[t];
}

// ---------------------------------------------------------------------------
// Kernel 2: main decoder. Grid = (ceil(G/GT), NB). One batch x one gene tile
// per block; A tile staged in shared (read from DRAM exactly once), W folded
// into packed f32x2 registers, cells streamed through shared with padded
// stride 32 so the dot is 8 LDS.128 + 16 FFMA2 per (cell, gene).
// ---------------------------------------------------------------------------
__global__ __launch_bounds__(GT)
void decoder_kernel(const float* __restrict__ z,
                    const float* __restrict__ sf,
                    const float* __restrict__ W,
                    const float* __restrict__ A,
                    const float* __restrict__ bemb,
                    float* __restrict__ out) {
    __shared__ float Ash[GT * LL];   // 30720 B
    __shared__ float zsh[CH * LP];   // 4096 B, float4-aligned rows
    __shared__ float sfsh[CH];
    __shared__ int   nsh[CH];

    const int tid = threadIdx.x;
    const int g0  = blockIdx.x * GT;
    const int b   = blockIdx.y;
    const int gt  = min(GT, GG - g0);

    const int g   = g0 + tid;
    const bool act = (tid < gt);

    // Prefetch W row-slices + bias BEFORE the barrier (overlaps A staging)
    float Wr[LL];
    float bb = 0.f;
    if (act) {
#pragma unroll
        for (int l = 0; l < LL; l++) Wr[l] = W[l * GG + g];
        bb = bemb[(size_t)b * GG + g];
    }

    // Stage A tile: contiguous gt*30 floats, float4 coalesced
    {
        const float4* Abase = (const float4*)(A + ((size_t)b * GG + g0) * LL);
        float4* As4 = (float4*)Ash;
        const int n4 = (gt * LL) >> 2;   // gt even -> divisible by 4
        for (int i = tid; i < n4; i += GT) As4[i] = Abase[i];
    }
    __syncthreads();

    // Fold: C[l] = W[l,g] + A[b,g,l], packed into 16 f32x2 regs (2 zero pads)
    unsigned long long C2[LP / 2];
    if (act) {
        float Cr[LP];
#pragma unroll
        for (int l = 0; l < LL; l++) Cr[l] = Ash[tid * LL + l] + Wr[l];
        Cr[30] = 0.f; Cr[31] = 0.f;
#pragma unroll
        for (int q = 0; q < LP / 2; q++) PACK2(C2[q], Cr[2 * q], Cr[2 * q + 1]);
    }

    const int s = g_bstart[b];
    const int e = g_bstart[b + 1];

    for (int c0 = s; c0 < e; c0 += CH) {
        const int nch = min(CH, e - c0);
        __syncthreads();   // zsh reuse safety
        if (tid < nch) {
            int n = g_order[c0 + tid];
            nsh[tid]  = n;
            sfsh[tid] = sf[n];
        }
        __syncthreads();   // nsh visible for staging
        // stage z rows, padded stride LP=32, pad lanes zeroed
        for (int i = tid; i < nch * LP; i += GT) {
            int j = i >> 5, l = i & 31;
            zsh[i] = (l < LL) ? z[nsh[j] * LL + l] : 0.f;
        }
        __syncthreads();

        if (act) {
            for (int j = 0; j < nch; j++) {
                const float4* zp = (const float4*)(zsh + j * LP);
                unsigned long long acc_a = 0ULL, acc_b = 0ULL;  // (0.f, 0.f)
#pragma unroll
                for (int q = 0; q < 8; q++) {
                    float4 zv = zp[q];                     // broadcast LDS.128
                    unsigned long long zlo, zhi;
                    PACK2(zlo, zv.x, zv.y);
                    PACK2(zhi, zv.z, zv.w);
                    FMA2(acc_a, C2[2 * q],     zlo, acc_a);
                    FMA2(acc_b, C2[2 * q + 1], zhi, acc_b);
                }
                float a0, a1, b0, b1;
                UNPACK2(a0, a1, acc_a);
                UNPACK2(b0, b1, acc_b);
                float acc = ((a0 + a1) + (b0 + b1)) + bb;
                // softplus via MUFU: |acc| < ~3 here, fully stable form anyway
                float sp = fmaxf(acc, 0.f) + __logf(1.f + __expf(-fabsf(acc)));
                out[(size_t)nsh[j] * GG + g] = sp * sfsh[j];
            }
        }
    }
}

// ---------------------------------------------------------------------------
// Launch. Inputs per metadata order:
//   0: z [N,L] f32        1: batch_covariate [N] i32   2: size_factor [N,1] f32
//   3: W_amat [L,G] f32   4: A_emb [NB,G,L] f32        5: b_emb [NB,G] f32
//   6: px_r [G] f32
// Output: mean [N,G] f32 followed by inverse_dispersion [G] f32.
// ---------------------------------------------------------------------------
extern "C" void kernel_launch(void* const* d_in, const int* in_sizes, int n_in,
                              void* d_out, int out_size) {
    const float* z    = (const float*)d_in[0];
    const int*   bc   = (const int*)  d_in[1];
    const float* sf   = (const float*)d_in[2];
    const float* W    = (const float*)d_in[3];
    const float* A    = (const float*)d_in[4];
    const float* bemb = (const float*)d_in[5];
    const float* pxr  = (const float*)d_in[6];
    float* out = (float*)d_out;

    prep_kernel<<<41, 256>>>(bc, pxr, out);

    dim3 grid((GG + GT - 1) / GT, NBATCH);
    decoder_kernel<<<grid, GT>>>(z, sf, W, A, bemb, out);
}